// round 10
// baseline (speedup 1.0000x reference)
#include <cuda_runtime.h>
#include <cuda_fp16.h>
#include <cuda_bf16.h>

// RoIAlign: features [4,1024,64,64] f32, rois [2048,5] f32 -> out [2048,1024,7,7] f32
//
// Geom prekernel precomputes per (roi,bin): smem site, output offset, 4
// bilinear weights as half2 (zeroed if invalid) -- AND permutes entries
// within each 32-entry chunk so lane p's site bank-group == p mod 8
// (greedy slotting). Within-warp permutation is free for STG/LDG coalescing
// (sectors unchanged) but makes each 8-lane LDS.128 phase near conflict-free.
// Main kernel: block = (batch, 8-ch chunk, slice), 1024 thr, 65KB fp16
// channel-interleaved smem (2 CTAs/SM). Per entry (8 outputs): 1 LDG.128
// (prefetched) + 4 LDS.128 + 16 HFMA2 + 8 F2F + 8 coalesced STG.32.

#define B_    4
#define C_    1024
#define H_    64
#define W_    64
#define N_    2048
#define BINS  49
#define SCALE 0.0625f

#define CH       8
#define PLANE4   65                         // uint4-site row stride
#define SMEM_BYTES (H_ * PLANE4 * 16)       // 66560 B
#define NTHREADS 1024
#define SLICES   2

__device__ int   g_roi_list[B_][N_];
__device__ int   g_roi_cnt[B_];
__device__ uint4 g_geom[B_][N_ * BINS];

__global__ void zero_cnt_kernel() {
    if (threadIdx.x < B_) g_roi_cnt[threadIdx.x] = 0;
}

__global__ void build_list_kernel(const float* __restrict__ rois) {
    int n = blockIdx.x * blockDim.x + threadIdx.x;
    if (n < N_) {
        int b = (int)rois[n * 5];
        int pos = atomicAdd(&g_roi_cnt[b], 1);
        g_roi_list[b][pos] = n;
    }
}

__global__ void geom_kernel(const float* __restrict__ rois) {
    __shared__ unsigned char s_grp[256];
    __shared__ unsigned char s_pos[256];

    const int tid = threadIdx.x;
    const int idx = blockIdx.x * 256 + tid;      // 0 .. N_*BINS-1
    const int b   = blockIdx.y;
    const int cnt = g_roi_cnt[b];

    uint4 e = make_uint4(0u, 0u, 0u, 0u);
    int grp = 8;                                 // sentinel: absent
    bool active = false;

    if (idx < N_ * BINS) {
        int slot = idx / BINS;
        int bin  = idx - slot * BINS;
        if (slot < cnt) {
            active = true;
            int n = g_roi_list[b][slot];
            const float* rp = rois + n * 5;
            float x1 = rp[1] * SCALE;
            float y1 = rp[2] * SCALE;
            float x2 = rp[3] * SCALE;
            float y2 = rp[4] * SCALE;
            float bw = fmaxf(x2 - x1, 0.0f) * (1.0f / 6.0f);
            float bh = fmaxf(y2 - y1, 0.0f) * (1.0f / 6.0f);
            float phf = (float)(bin / 7);
            float pwf = (float)(bin % 7);
            float h = y1 + phf * bh;
            float w = x1 + pwf * bw;

            float hstart = fminf(floorf(h), (float)(H_ - 2));
            float wstart = fminf(floorf(w), (float)(W_ - 2));
            float hr = h - hstart;
            float wr = w - wstart;
            bool valid = (h >= 0.0f) && (h < (float)H_) &&
                         (w >= 0.0f) && (w < (float)W_);
            int hs = min(max((int)hstart, 0), H_ - 2);
            int ws = min(max((int)wstart, 0), W_ - 2);

            float omh = 1.0f - hr, omw = 1.0f - wr;
            float wa = omh * omw;
            float wb = omh * wr;
            float wc = hr * omw;
            float wd = hr * wr;
            if (!valid) { wa = wb = wc = wd = 0.0f; }

            __half2 hab = __floats2half2_rn(wa, wb);
            __half2 hcd = __floats2half2_rn(wc, wd);

            int site = hs * PLANE4 + ws;
            e.x = (unsigned)site;
            e.y = (unsigned)(n * (C_ * BINS) + bin);
            e.z = *reinterpret_cast<unsigned*>(&hab);
            e.w = *reinterpret_cast<unsigned*>(&hcd);
            grp = site & 7;
        }
    }

    s_grp[tid] = (unsigned char)grp;
    s_pos[tid] = (unsigned char)(tid & 31);      // default: identity
    __syncthreads();

    // lane 0 of each warp: greedy bank-group slotting for its 32-entry chunk
    if ((tid & 31) == 0) {
        int base = tid;
        bool full = true;
        for (int j = 0; j < 32; j++)
            if (s_grp[base + j] == 8) { full = false; break; }
        if (full) {
            unsigned taken = 0;
            unsigned char pos[32];
            for (int j = 0; j < 32; j++) pos[j] = 255;
            for (int j = 0; j < 32; j++) {
                int g = s_grp[base + j];
                #pragma unroll
                for (int k = 0; k < 4; k++) {
                    int p = g + 8 * k;
                    if (!((taken >> p) & 1u)) { pos[j] = (unsigned char)p;
                                                taken |= 1u << p; break; }
                }
            }
            for (int j = 0; j < 32; j++) {
                if (pos[j] == 255) {
                    for (int p = 0; p < 32; p++)
                        if (!((taken >> p) & 1u)) { pos[j] = (unsigned char)p;
                                                    taken |= 1u << p; break; }
                }
            }
            for (int j = 0; j < 32; j++) s_pos[base + j] = pos[j];
        }
    }
    __syncthreads();

    if (active) {
        int chunk_base = idx & ~31;
        g_geom[b][chunk_base + s_pos[tid]] = e;
    }
}

__global__ __launch_bounds__(NTHREADS, 2)
void roialign_kernel(const float* __restrict__ features,
                     float* __restrict__ out) {
    extern __shared__ uint4 sm[];                 // [hs*65+ws] -> 8 fp16 ch

    const int b     = blockIdx.y;
    const int c0    = (blockIdx.x >> 1) * CH;
    const int slice = blockIdx.x & (SLICES - 1);

    // ---- Stage: 8 coalesced channel streams -> fp16 interleaved ----
    {
        const float* src = features + (size_t)(b * C_ + c0) * (H_ * W_);
        #pragma unroll
        for (int k = 0; k < (H_ * W_) / NTHREADS; k++) {
            int i = k * NTHREADS + threadIdx.x;
            int row = i >> 6;
            int col = i & 63;
            __half2 h01 = __floats2half2_rn(src[i],            src[1 * 4096 + i]);
            __half2 h23 = __floats2half2_rn(src[2 * 4096 + i], src[3 * 4096 + i]);
            __half2 h45 = __floats2half2_rn(src[4 * 4096 + i], src[5 * 4096 + i]);
            __half2 h67 = __floats2half2_rn(src[6 * 4096 + i], src[7 * 4096 + i]);
            uint4 v;
            v.x = *reinterpret_cast<unsigned*>(&h01);
            v.y = *reinterpret_cast<unsigned*>(&h23);
            v.z = *reinterpret_cast<unsigned*>(&h45);
            v.w = *reinterpret_cast<unsigned*>(&h67);
            sm[row * PLANE4 + col] = v;
        }
    }
    __syncthreads();

    const int E    = g_roi_cnt[b] * BINS;
    const int lane = threadIdx.x & 31;
    const int warp = threadIdx.x >> 5;            // 0..31

    const uint4* __restrict__ gt = g_geom[b];
    float* __restrict__ obase = out + (size_t)c0 * BINS;

    int base0 = (slice * 32 + warp) * 32;
    uint4 gnext = (base0 + lane < E) ? __ldg(&gt[base0 + lane])
                                     : make_uint4(0u, 0u, 0u, 0u);

    for (int base = base0; base < E; base += SLICES * NTHREADS) {
        uint4 g = gnext;
        int nx = base + SLICES * NTHREADS + lane;
        if (nx < E) gnext = __ldg(&gt[nx]);

        if (base + lane < E) {
            int s = (int)(g.x & 8191u);

            __half2 wab = *reinterpret_cast<__half2*>(&g.z);
            __half2 wcd = *reinterpret_cast<__half2*>(&g.w);
            __half2 waa = __half2half2(__low2half(wab));
            __half2 wbb = __half2half2(__high2half(wab));
            __half2 wcc = __half2half2(__low2half(wcd));
            __half2 wdd = __half2half2(__high2half(wcd));

            uint4 ul = sm[s];
            uint4 ur = sm[s + 1];
            uint4 dl = sm[s + PLANE4];
            uint4 dr = sm[s + PLANE4 + 1];

            float* o = obase + g.y;

            const unsigned* pul = &ul.x;
            const unsigned* pur = &ur.x;
            const unsigned* pdl = &dl.x;
            const unsigned* pdr = &dr.x;
            #pragma unroll
            for (int j = 0; j < 4; j++) {
                __half2 acc = __hmul2(*reinterpret_cast<const __half2*>(&pul[j]), waa);
                acc = __hfma2(*reinterpret_cast<const __half2*>(&pur[j]), wbb, acc);
                acc = __hfma2(*reinterpret_cast<const __half2*>(&pdl[j]), wcc, acc);
                acc = __hfma2(*reinterpret_cast<const __half2*>(&pdr[j]), wdd, acc);
                float2 f = __half22float2(acc);
                o[(2 * j)     * BINS] = f.x;
                o[(2 * j + 1) * BINS] = f.y;
            }
        }
    }
}

extern "C" void kernel_launch(void* const* d_in, const int* in_sizes, int n_in,
                              void* d_out, int out_size) {
    const float* features = (const float*)d_in[0];
    const float* rois     = (const float*)d_in[1];
    float* out            = (float*)d_out;

    cudaFuncSetAttribute(roialign_kernel,
                         cudaFuncAttributeMaxDynamicSharedMemorySize,
                         SMEM_BYTES);

    zero_cnt_kernel<<<1, 32>>>();
    build_list_kernel<<<N_ / 256, 256>>>(rois);
    {
        dim3 g((N_ * BINS + 255) / 256, B_);
        geom_kernel<<<g, 256>>>(rois);
    }
    {
        dim3 g((C_ / CH) * SLICES, B_);
        roialign_kernel<<<g, NTHREADS, SMEM_BYTES>>>(features, out);
    }
}

// round 11
// speedup vs baseline: 1.0626x; 1.0626x over previous
#include <cuda_runtime.h>
#include <cuda_fp16.h>
#include <cuda_bf16.h>

// RoIAlign: features [4,1024,64,64] f32, rois [2048,5] f32 -> out [2048,1024,7,7] f32
//
// Geom prekernel precomputes per (roi,bin): smem site, output offset, 4
// bilinear weights as half2 (zeroed if invalid). Main kernel: block =
// (batch, 8-ch chunk, slice), 1024 thr, 65KB fp16 channel-interleaved smem
// (2 CTAs/SM). Per entry (8 outputs): 1 LDG.128 (L1-prefetched 2 iterations
// ahead via prefetch.global.L1 -- the kernel was latency-bound on this load)
// + 4 LDS.128 + 16 HFMA2 + 8 F2F + 8 coalesced streaming STG.32 (__stcs).
// Roi-count zeroing via cudaMemsetAsync (no 32-thread launch).

#define B_    4
#define C_    1024
#define H_    64
#define W_    64
#define N_    2048
#define BINS  49
#define SCALE 0.0625f

#define CH       8
#define PLANE4   65                         // uint4-site row stride
#define SMEM_BYTES (H_ * PLANE4 * 16)       // 66560 B
#define NTHREADS 1024
#define SLICES   2

__device__ int   g_roi_list[B_][N_];
__device__ int   g_roi_cnt[B_];
__device__ uint4 g_geom[B_][N_ * BINS];

__global__ void build_list_kernel(const float* __restrict__ rois) {
    int n = blockIdx.x * blockDim.x + threadIdx.x;
    if (n < N_) {
        int b = (int)rois[n * 5];
        int pos = atomicAdd(&g_roi_cnt[b], 1);
        g_roi_list[b][pos] = n;
    }
}

__global__ void geom_kernel(const float* __restrict__ rois) {
    int idx = blockIdx.x * 256 + threadIdx.x;      // 0 .. N_*BINS-1
    int b = blockIdx.y;
    if (idx >= N_ * BINS) return;
    int slot = idx / BINS;
    int bin  = idx - slot * BINS;
    if (slot >= g_roi_cnt[b]) return;
    int n = g_roi_list[b][slot];

    const float* rp = rois + n * 5;
    float x1 = rp[1] * SCALE;
    float y1 = rp[2] * SCALE;
    float x2 = rp[3] * SCALE;
    float y2 = rp[4] * SCALE;
    float bw = fmaxf(x2 - x1, 0.0f) * (1.0f / 6.0f);
    float bh = fmaxf(y2 - y1, 0.0f) * (1.0f / 6.0f);
    float phf = (float)(bin / 7);
    float pwf = (float)(bin % 7);
    float h = y1 + phf * bh;
    float w = x1 + pwf * bw;

    float hstart = fminf(floorf(h), (float)(H_ - 2));
    float wstart = fminf(floorf(w), (float)(W_ - 2));
    float hr = h - hstart;
    float wr = w - wstart;
    bool valid = (h >= 0.0f) && (h < (float)H_) &&
                 (w >= 0.0f) && (w < (float)W_);
    int hs = min(max((int)hstart, 0), H_ - 2);
    int ws = min(max((int)wstart, 0), W_ - 2);

    float omh = 1.0f - hr, omw = 1.0f - wr;
    float wa = omh * omw;
    float wb = omh * wr;
    float wc = hr * omw;
    float wd = hr * wr;
    if (!valid) { wa = wb = wc = wd = 0.0f; }

    __half2 hab = __floats2half2_rn(wa, wb);
    __half2 hcd = __floats2half2_rn(wc, wd);

    uint4 e;
    e.x = (unsigned)(hs * PLANE4 + ws);
    e.y = (unsigned)(n * (C_ * BINS) + bin);
    e.z = *reinterpret_cast<unsigned*>(&hab);
    e.w = *reinterpret_cast<unsigned*>(&hcd);
    g_geom[b][idx] = e;
}

__global__ __launch_bounds__(NTHREADS, 2)
void roialign_kernel(const float* __restrict__ features,
                     float* __restrict__ out) {
    extern __shared__ uint4 sm[];                 // [hs*65+ws] -> 8 fp16 ch

    const int b     = blockIdx.y;
    const int c0    = (blockIdx.x >> 1) * CH;
    const int slice = blockIdx.x & (SLICES - 1);

    // ---- Stage: 8 coalesced channel streams -> fp16 interleaved ----
    {
        const float* src = features + (size_t)(b * C_ + c0) * (H_ * W_);
        #pragma unroll
        for (int k = 0; k < (H_ * W_) / NTHREADS; k++) {
            int i = k * NTHREADS + threadIdx.x;
            int row = i >> 6;
            int col = i & 63;
            __half2 h01 = __floats2half2_rn(src[i],            src[1 * 4096 + i]);
            __half2 h23 = __floats2half2_rn(src[2 * 4096 + i], src[3 * 4096 + i]);
            __half2 h45 = __floats2half2_rn(src[4 * 4096 + i], src[5 * 4096 + i]);
            __half2 h67 = __floats2half2_rn(src[6 * 4096 + i], src[7 * 4096 + i]);
            uint4 v;
            v.x = *reinterpret_cast<unsigned*>(&h01);
            v.y = *reinterpret_cast<unsigned*>(&h23);
            v.z = *reinterpret_cast<unsigned*>(&h45);
            v.w = *reinterpret_cast<unsigned*>(&h67);
            sm[row * PLANE4 + col] = v;
        }
    }
    __syncthreads();

    const int E    = g_roi_cnt[b] * BINS;
    const int lane = threadIdx.x & 31;
    const int warp = threadIdx.x >> 5;            // 0..31

    const uint4* __restrict__ gt = g_geom[b];
    float* __restrict__ obase = out + (size_t)c0 * BINS;

    const int STRIDE = SLICES * NTHREADS;         // 2048 entries
    int base0 = (slice * 32 + warp) * 32;

    uint4 gnext = (base0 + lane < E) ? __ldg(&gt[base0 + lane])
                                     : make_uint4(0u, 0u, 0u, 0u);
    // warm L1 for the following chunk
    asm volatile("prefetch.global.L1 [%0];" :: "l"(gt + base0 + STRIDE + lane));

    for (int base = base0; base < E; base += STRIDE) {
        uint4 g = gnext;
        int nx = base + STRIDE + lane;
        if (nx < E) gnext = __ldg(&gt[nx]);
        // prefetch two chunks ahead so the next LDG is an L1 hit
        asm volatile("prefetch.global.L1 [%0];"
                     :: "l"(gt + base + 2 * STRIDE + lane));

        if (base + lane < E) {
            int s = (int)g.x;

            __half2 wab = *reinterpret_cast<__half2*>(&g.z);
            __half2 wcd = *reinterpret_cast<__half2*>(&g.w);
            __half2 waa = __half2half2(__low2half(wab));
            __half2 wbb = __half2half2(__high2half(wab));
            __half2 wcc = __half2half2(__low2half(wcd));
            __half2 wdd = __half2half2(__high2half(wcd));

            uint4 ul = sm[s];
            uint4 ur = sm[s + 1];
            uint4 dl = sm[s + PLANE4];
            uint4 dr = sm[s + PLANE4 + 1];

            float* o = obase + g.y;

            const unsigned* pul = &ul.x;
            const unsigned* pur = &ur.x;
            const unsigned* pdl = &dl.x;
            const unsigned* pdr = &dr.x;
            #pragma unroll
            for (int j = 0; j < 4; j++) {
                __half2 acc = __hmul2(*reinterpret_cast<const __half2*>(&pul[j]), waa);
                acc = __hfma2(*reinterpret_cast<const __half2*>(&pur[j]), wbb, acc);
                acc = __hfma2(*reinterpret_cast<const __half2*>(&pdl[j]), wcc, acc);
                acc = __hfma2(*reinterpret_cast<const __half2*>(&pdr[j]), wdd, acc);
                float2 f = __half22float2(acc);
                __stcs(&o[(2 * j)     * BINS], f.x);
                __stcs(&o[(2 * j + 1) * BINS], f.y);
            }
        }
    }
}

extern "C" void kernel_launch(void* const* d_in, const int* in_sizes, int n_in,
                              void* d_out, int out_size) {
    const float* features = (const float*)d_in[0];
    const float* rois     = (const float*)d_in[1];
    float* out            = (float*)d_out;

    cudaFuncSetAttribute(roialign_kernel,
                         cudaFuncAttributeMaxDynamicSharedMemorySize,
                         SMEM_BYTES);

    void* cnt_ptr = nullptr;
    cudaGetSymbolAddress(&cnt_ptr, g_roi_cnt);
    cudaMemsetAsync(cnt_ptr, 0, B_ * sizeof(int));

    build_list_kernel<<<N_ / 256, 256>>>(rois);
    {
        dim3 g((N_ * BINS + 255) / 256, B_);
        geom_kernel<<<g, 256>>>(rois);
    }
    {
        dim3 g((C_ / CH) * SLICES, B_);
        roialign_kernel<<<g, NTHREADS, SMEM_BYTES>>>(features, out);
    }
}

// round 12
// speedup vs baseline: 1.1361x; 1.0692x over previous
#include <cuda_runtime.h>
#include <cuda_fp16.h>
#include <cuda_bf16.h>

// RoIAlign: features [4,1024,64,64] f32, rois [2048,5] f32 -> out [2048,1024,7,7] f32
//
// Geom prekernel precomputes per (roi,bin): smem site, output offset, 4
// bilinear weights as half2 (zeroed if invalid). Main kernel: block =
// (batch, 8-ch chunk, slice), 768 threads, 65KB fp16 channel-interleaved
// smem, 2 CTAs/SM -> 1536 thr/SM -> 42 regs/thread (vs 32 at 1024 thr:
// the 32-reg cap forced ptxas to serialize the 4 corner LDS.128 loads,
// exposing ~4x29cy of LDS latency per iteration -- the invariant ~119us
// across all L1-load changes). Per entry (8 outputs): 1 LDG.128
// (register-pipelined) + 4 LDS.128 + 16 HFMA2 + 8 F2F + 8 coalesced STG.32.

#define B_    4
#define C_    1024
#define H_    64
#define W_    64
#define N_    2048
#define BINS  49
#define SCALE 0.0625f

#define CH       8
#define PLANE4   65                         // uint4-site row stride
#define SMEM_BYTES (H_ * PLANE4 * 16)       // 66560 B
#define NTHREADS 768
#define WPB      (NTHREADS / 32)            // 24 warps
#define SLICES   2

__device__ int   g_roi_list[B_][N_];
__device__ int   g_roi_cnt[B_];
__device__ uint4 g_geom[B_][N_ * BINS];

__global__ void build_list_kernel(const float* __restrict__ rois) {
    int n = blockIdx.x * blockDim.x + threadIdx.x;
    if (n < N_) {
        int b = (int)rois[n * 5];
        int pos = atomicAdd(&g_roi_cnt[b], 1);
        g_roi_list[b][pos] = n;
    }
}

__global__ void geom_kernel(const float* __restrict__ rois) {
    int idx = blockIdx.x * 256 + threadIdx.x;      // 0 .. N_*BINS-1
    int b = blockIdx.y;
    if (idx >= N_ * BINS) return;
    int slot = idx / BINS;
    int bin  = idx - slot * BINS;
    if (slot >= g_roi_cnt[b]) return;
    int n = g_roi_list[b][slot];

    const float* rp = rois + n * 5;
    float x1 = rp[1] * SCALE;
    float y1 = rp[2] * SCALE;
    float x2 = rp[3] * SCALE;
    float y2 = rp[4] * SCALE;
    float bw = fmaxf(x2 - x1, 0.0f) * (1.0f / 6.0f);
    float bh = fmaxf(y2 - y1, 0.0f) * (1.0f / 6.0f);
    float phf = (float)(bin / 7);
    float pwf = (float)(bin % 7);
    float h = y1 + phf * bh;
    float w = x1 + pwf * bw;

    float hstart = fminf(floorf(h), (float)(H_ - 2));
    float wstart = fminf(floorf(w), (float)(W_ - 2));
    float hr = h - hstart;
    float wr = w - wstart;
    bool valid = (h >= 0.0f) && (h < (float)H_) &&
                 (w >= 0.0f) && (w < (float)W_);
    int hs = min(max((int)hstart, 0), H_ - 2);
    int ws = min(max((int)wstart, 0), W_ - 2);

    float omh = 1.0f - hr, omw = 1.0f - wr;
    float wa = omh * omw;
    float wb = omh * wr;
    float wc = hr * omw;
    float wd = hr * wr;
    if (!valid) { wa = wb = wc = wd = 0.0f; }

    __half2 hab = __floats2half2_rn(wa, wb);
    __half2 hcd = __floats2half2_rn(wc, wd);

    uint4 e;
    e.x = (unsigned)(hs * PLANE4 + ws);
    e.y = (unsigned)(n * (C_ * BINS) + bin);
    e.z = *reinterpret_cast<unsigned*>(&hab);
    e.w = *reinterpret_cast<unsigned*>(&hcd);
    g_geom[b][idx] = e;
}

__global__ __launch_bounds__(NTHREADS, 2)
void roialign_kernel(const float* __restrict__ features,
                     float* __restrict__ out) {
    extern __shared__ uint4 sm[];                 // [hs*65+ws] -> 8 fp16 ch

    const int b     = blockIdx.y;
    const int c0    = (blockIdx.x >> 1) * CH;
    const int slice = blockIdx.x & (SLICES - 1);

    // ---- Stage: 8 coalesced channel streams -> fp16 interleaved ----
    {
        const float* src = features + (size_t)(b * C_ + c0) * (H_ * W_);
        #pragma unroll
        for (int k = 0; k < 6; k++) {
            int i = k * NTHREADS + threadIdx.x;
            if (i < H_ * W_) {
                int row = i >> 6;
                int col = i & 63;
                __half2 h01 = __floats2half2_rn(src[i],            src[1 * 4096 + i]);
                __half2 h23 = __floats2half2_rn(src[2 * 4096 + i], src[3 * 4096 + i]);
                __half2 h45 = __floats2half2_rn(src[4 * 4096 + i], src[5 * 4096 + i]);
                __half2 h67 = __floats2half2_rn(src[6 * 4096 + i], src[7 * 4096 + i]);
                uint4 v;
                v.x = *reinterpret_cast<unsigned*>(&h01);
                v.y = *reinterpret_cast<unsigned*>(&h23);
                v.z = *reinterpret_cast<unsigned*>(&h45);
                v.w = *reinterpret_cast<unsigned*>(&h67);
                sm[row * PLANE4 + col] = v;
            }
        }
    }
    __syncthreads();

    const int E    = g_roi_cnt[b] * BINS;
    const int lane = threadIdx.x & 31;
    const int warp = threadIdx.x >> 5;            // 0..23

    const uint4* __restrict__ gt = g_geom[b];
    float* __restrict__ obase = out + (size_t)c0 * BINS;

    const int STRIDE = SLICES * WPB * 32;         // 1536 entries
    int base0 = (slice * WPB + warp) * 32;

    uint4 gnext = (base0 + lane < E) ? __ldg(&gt[base0 + lane])
                                     : make_uint4(0u, 0u, 0u, 0u);

    for (int base = base0; base < E; base += STRIDE) {
        uint4 g = gnext;
        int nx = base + STRIDE + lane;
        if (nx < E) gnext = __ldg(&gt[nx]);

        if (base + lane < E) {
            int s = (int)g.x;

            __half2 wab = *reinterpret_cast<__half2*>(&g.z);
            __half2 wcd = *reinterpret_cast<__half2*>(&g.w);
            __half2 waa = __half2half2(__low2half(wab));
            __half2 wbb = __half2half2(__high2half(wab));
            __half2 wcc = __half2half2(__low2half(wcd));
            __half2 wdd = __half2half2(__high2half(wcd));

            uint4 ul = sm[s];
            uint4 ur = sm[s + 1];
            uint4 dl = sm[s + PLANE4];
            uint4 dr = sm[s + PLANE4 + 1];

            float* o = obase + g.y;

            const unsigned* pul = &ul.x;
            const unsigned* pur = &ur.x;
            const unsigned* pdl = &dl.x;
            const unsigned* pdr = &dr.x;
            #pragma unroll
            for (int j = 0; j < 4; j++) {
                __half2 acc = __hmul2(*reinterpret_cast<const __half2*>(&pul[j]), waa);
                acc = __hfma2(*reinterpret_cast<const __half2*>(&pur[j]), wbb, acc);
                acc = __hfma2(*reinterpret_cast<const __half2*>(&pdl[j]), wcc, acc);
                acc = __hfma2(*reinterpret_cast<const __half2*>(&pdr[j]), wdd, acc);
                float2 f = __half22float2(acc);
                o[(2 * j)     * BINS] = f.x;
                o[(2 * j + 1) * BINS] = f.y;
            }
        }
    }
}

extern "C" void kernel_launch(void* const* d_in, const int* in_sizes, int n_in,
                              void* d_out, int out_size) {
    const float* features = (const float*)d_in[0];
    const float* rois     = (const float*)d_in[1];
    float* out            = (float*)d_out;

    cudaFuncSetAttribute(roialign_kernel,
                         cudaFuncAttributeMaxDynamicSharedMemorySize,
                         SMEM_BYTES);

    void* cnt_ptr = nullptr;
    cudaGetSymbolAddress(&cnt_ptr, g_roi_cnt);
    cudaMemsetAsync(cnt_ptr, 0, B_ * sizeof(int));

    build_list_kernel<<<N_ / 256, 256>>>(rois);
    {
        dim3 g((N_ * BINS + 255) / 256, B_);
        geom_kernel<<<g, 256>>>(rois);
    }
    {
        dim3 g((C_ / CH) * SLICES, B_);
        roialign_kernel<<<g, NTHREADS, SMEM_BYTES>>>(features, out);
    }
}